// round 2
// baseline (speedup 1.0000x reference)
#include <cuda_runtime.h>
#include <cuda_bf16.h>
#include <math.h>

// ---------------------------------------------------------------------------
// Problem constants
// ---------------------------------------------------------------------------
#define BATCH 4
#define SEQ 64
#define PAST 2048
#define TTOT 2112            // PAST + SEQ
#define HIDDEN 2048
#define NQ 16
#define NKV 4
#define HDIM 128
#define INTER 8192
#define VOCAB 32000
#define ROWS 256             // B*S
#define EPS 1e-6f

#define LOGITS_ELEMS (ROWS * VOCAB)                  // 8,192,000
#define GATHERED_ELEMS (ROWS * HIDDEN)               // 524,288
#define PRESENT_OFF (LOGITS_ELEMS + GATHERED_ELEMS)  // 8,716,288

// ---------------------------------------------------------------------------
// Scratch (device globals; no runtime allocation)
// ---------------------------------------------------------------------------
__device__ float g_hs[ROWS * HIDDEN];
__device__ float g_normed[ROWS * 2 * HIDDEN];
__device__ float g_q[ROWS * NQ * HDIM];
__device__ float g_k[ROWS * NKV * HDIM];
__device__ float g_v[ROWS * NKV * HDIM];
__device__ float g_attn[ROWS * NQ * HDIM];
__device__ float g_hn[ROWS * HIDDEN];
__device__ float g_gate[ROWS * INTER];
__device__ float g_act[ROWS * INTER];
__device__ float g_fn[ROWS * HIDDEN];

// ---------------------------------------------------------------------------
// Block reductions (256 threads)
// ---------------------------------------------------------------------------
__device__ __forceinline__ float block_sum(float v) {
    __shared__ float sh[8];
    __shared__ float total;
    int tid = threadIdx.x;
#pragma unroll
    for (int o = 16; o > 0; o >>= 1) v += __shfl_xor_sync(0xffffffffu, v, o);
    if ((tid & 31) == 0) sh[tid >> 5] = v;
    __syncthreads();
    if (tid == 0) {
        float s = 0.f;
#pragma unroll
        for (int i = 0; i < 8; i++) s += sh[i];
        total = s;
    }
    __syncthreads();
    float r = total;
    __syncthreads();   // allow re-entry
    return r;
}

__device__ __forceinline__ float block_max(float v) {
    __shared__ float sh[8];
    __shared__ float total;
    int tid = threadIdx.x;
#pragma unroll
    for (int o = 16; o > 0; o >>= 1) v = fmaxf(v, __shfl_xor_sync(0xffffffffu, v, o));
    if ((tid & 31) == 0) sh[tid >> 5] = v;
    __syncthreads();
    if (tid == 0) {
        float s = -INFINITY;
#pragma unroll
        for (int i = 0; i < 8; i++) s = fmaxf(s, sh[i]);
        total = s;
    }
    __syncthreads();
    float r = total;
    __syncthreads();
    return r;
}

// ---------------------------------------------------------------------------
// Tiled SGEMM 128x128x8, 256 threads, 8x8 per thread, fp32.
// C[M,N] = A[M,K] @ B[K,N]  (+ epilogue)
//   EPI 0: C = acc
//   EPI 1: C = acc + Aux   (residual, Aux same layout as C; Aux may alias C)
//   EPI 2: C = silu(Aux) * acc
// Requires: M % 128 == 0, N % 128 == 0, K % 8 == 0.
// ---------------------------------------------------------------------------
template <int EPI>
__global__ void __launch_bounds__(256) sgemm128(
    const float* __restrict__ A, const float* __restrict__ B,
    float* __restrict__ C, const float* __restrict__ Aux,
    int M, int N, int K)
{
    __shared__ float As[8][128];
    __shared__ float Bs[8][128];

    const int bx = blockIdx.x;   // N block
    const int by = blockIdx.y;   // M block
    const int tid = threadIdx.x;

    const float* Ag = A + (size_t)by * 128 * K;
    const float* Bg = B + (size_t)bx * 128;

    const int aRow  = tid >> 1;          // 0..127
    const int aCol4 = (tid & 1) * 4;     // 0 or 4
    const int bRow  = tid >> 5;          // 0..7
    const int bCol4 = (tid & 31) * 4;    // 0..124

    const int tRow = (tid >> 4) * 8;
    const int tCol = (tid & 15) * 8;

    float acc[8][8];
#pragma unroll
    for (int i = 0; i < 8; i++)
#pragma unroll
        for (int j = 0; j < 8; j++) acc[i][j] = 0.f;

    for (int k0 = 0; k0 < K; k0 += 8) {
        float4 av = *reinterpret_cast<const float4*>(Ag + (size_t)aRow * K + k0 + aCol4);
        float4 bv = *reinterpret_cast<const float4*>(Bg + (size_t)(k0 + bRow) * N + bCol4);
        __syncthreads();
        As[aCol4 + 0][aRow] = av.x;
        As[aCol4 + 1][aRow] = av.y;
        As[aCol4 + 2][aRow] = av.z;
        As[aCol4 + 3][aRow] = av.w;
        *reinterpret_cast<float4*>(&Bs[bRow][bCol4]) = bv;
        __syncthreads();
#pragma unroll
        for (int k = 0; k < 8; k++) {
            float ar[8], br[8];
            float4 a0 = *reinterpret_cast<const float4*>(&As[k][tRow]);
            float4 a1 = *reinterpret_cast<const float4*>(&As[k][tRow + 4]);
            float4 b0 = *reinterpret_cast<const float4*>(&Bs[k][tCol]);
            float4 b1 = *reinterpret_cast<const float4*>(&Bs[k][tCol + 4]);
            ar[0]=a0.x; ar[1]=a0.y; ar[2]=a0.z; ar[3]=a0.w;
            ar[4]=a1.x; ar[5]=a1.y; ar[6]=a1.z; ar[7]=a1.w;
            br[0]=b0.x; br[1]=b0.y; br[2]=b0.z; br[3]=b0.w;
            br[4]=b1.x; br[5]=b1.y; br[6]=b1.z; br[7]=b1.w;
#pragma unroll
            for (int i = 0; i < 8; i++)
#pragma unroll
                for (int j = 0; j < 8; j++)
                    acc[i][j] = fmaf(ar[i], br[j], acc[i][j]);
        }
    }

    const int cRowBase = by * 128 + tRow;
    const int cColBase = bx * 128 + tCol;
#pragma unroll
    for (int i = 0; i < 8; i++) {
        size_t roff = (size_t)(cRowBase + i) * N + cColBase;
        float* Crow = C + roff;
#pragma unroll
        for (int j = 0; j < 8; j++) {
            float v = acc[i][j];
            if constexpr (EPI == 1) {
                v += Aux[roff + j];
            } else if constexpr (EPI == 2) {
                float gv = Aux[roff + j];
                v = (gv / (1.f + expf(-gv))) * v;
            }
            Crow[j] = v;
        }
    }
}

// ---------------------------------------------------------------------------
// Dual RMS norm + concat: normed[row] = [rms(emb)*w_in , rms(hs)*w_hid]
// ---------------------------------------------------------------------------
__global__ void __launch_bounds__(256) rms_concat_kernel(
    const float* __restrict__ emb, const float* __restrict__ hs,
    const float* __restrict__ w_in, const float* __restrict__ w_hid,
    float* __restrict__ normed)
{
    const int row = blockIdx.x;
    const int tid = threadIdx.x;
    const float* x1 = emb + (size_t)row * HIDDEN;
    const float* x2 = hs + (size_t)row * HIDDEN;
    float s1 = 0.f, s2 = 0.f;
    for (int i = tid; i < HIDDEN; i += 256) {
        float a = x1[i]; s1 += a * a;
        float b = x2[i]; s2 += b * b;
    }
    float r1 = block_sum(s1);
    float r2 = block_sum(s2);
    float inv1 = rsqrtf(r1 / (float)HIDDEN + EPS);
    float inv2 = rsqrtf(r2 / (float)HIDDEN + EPS);
    float* o = normed + (size_t)row * (2 * HIDDEN);
    for (int i = tid; i < HIDDEN; i += 256) {
        o[i]          = x1[i] * inv1 * w_in[i];
        o[HIDDEN + i] = x2[i] * inv2 * w_hid[i];
    }
}

// ---------------------------------------------------------------------------
// Single RMS norm
// ---------------------------------------------------------------------------
__global__ void __launch_bounds__(256) rms_kernel(
    const float* __restrict__ x, const float* __restrict__ w, float* __restrict__ y)
{
    const int row = blockIdx.x;
    const int tid = threadIdx.x;
    const float* xr = x + (size_t)row * HIDDEN;
    float s = 0.f;
    for (int i = tid; i < HIDDEN; i += 256) { float a = xr[i]; s += a * a; }
    float r = block_sum(s);
    float inv = rsqrtf(r / (float)HIDDEN + EPS);
    float* yr = y + (size_t)row * HIDDEN;
    for (int i = tid; i < HIDDEN; i += 256) yr[i] = xr[i] * inv * w[i];
}

// ---------------------------------------------------------------------------
// Gather by last_token_ids, write `gathered` output, and final RMS -> fn
// ---------------------------------------------------------------------------
__global__ void __launch_bounds__(256) gather_rms_kernel(
    const float* __restrict__ hs, const int* __restrict__ lt,
    const float* __restrict__ w, float* __restrict__ out_gathered,
    float* __restrict__ fn)
{
    const int row = blockIdx.x;   // b*SEQ + s
    const int tid = threadIdx.x;
    const int b = row >> 6;
    const int src_s = lt[row];
    const float* x = hs + ((size_t)b * SEQ + src_s) * HIDDEN;
    float s = 0.f;
    for (int i = tid; i < HIDDEN; i += 256) { float a = x[i]; s += a * a; }
    float r = block_sum(s);
    float inv = rsqrtf(r / (float)HIDDEN + EPS);
    float* og = out_gathered + (size_t)row * HIDDEN;
    float* fr = fn + (size_t)row * HIDDEN;
    for (int i = tid; i < HIDDEN; i += 256) {
        float a = x[i];
        og[i] = a;
        fr[i] = a * inv * w[i];
    }
}

// ---------------------------------------------------------------------------
// Copy past KV (B,2,NKV,PAST,128) into present (B,2,NKV,TTOT,128) output
// total float4 = 4*2*4*2048*128/4 = 2,097,152  -> grid 8192 x 256
// ---------------------------------------------------------------------------
__global__ void __launch_bounds__(256) copy_past_kernel(
    const float* __restrict__ past, float* __restrict__ present)
{
    const int idx = blockIdx.x * 256 + threadIdx.x;  // float4 index
    const int lane = idx & 31;
    const int row = idx >> 5;        // (b,c,h,t) with t fastest
    const int t = row & 2047;
    const int bch = row >> 11;
    const float4* src = reinterpret_cast<const float4*>(past) + idx;
    float4* dst = reinterpret_cast<float4*>(present) + ((size_t)bch * TTOT + t) * 32 + lane;
    *dst = *src;
}

// ---------------------------------------------------------------------------
// RoPE q (in place), RoPE k -> present, copy v -> present
// grid (256, 24), block 64
// ---------------------------------------------------------------------------
__global__ void __launch_bounds__(64) rope_store_kernel(
    float* __restrict__ q, const float* __restrict__ k, const float* __restrict__ v,
    const float* __restrict__ rope, const int* __restrict__ pos_ids,
    float* __restrict__ present)
{
    const int bs = blockIdx.x;
    const int h = blockIdx.y;
    const int d = threadIdx.x;     // 0..63
    const int b = bs >> 6, s = bs & 63;
    const int pos = pos_ids[bs];
    const float c = rope[(size_t)pos * 128 + d];
    const float sn = rope[(size_t)pos * 128 + 64 + d];
    if (h < 16) {
        float* base = q + ((size_t)bs * NQ + h) * HDIM;
        float x1 = base[d], x2 = base[d + 64];
        base[d] = x1 * c - x2 * sn;
        base[d + 64] = x2 * c + x1 * sn;
    } else if (h < 20) {
        const int kh = h - 16;
        const float* base = k + ((size_t)bs * NKV + kh) * HDIM;
        float x1 = base[d], x2 = base[d + 64];
        float* dst = present + (((size_t)(b * 2 + 0) * NKV + kh) * TTOT + PAST + s) * HDIM;
        dst[d] = x1 * c - x2 * sn;
        dst[d + 64] = x2 * c + x1 * sn;
    } else {
        const int vh = h - 20;
        const float* base = v + ((size_t)bs * NKV + vh) * HDIM;
        float* dst = present + (((size_t)(b * 2 + 1) * NKV + vh) * TTOT + PAST + s) * HDIM;
        dst[d] = base[d];
        dst[d + 64] = base[d + 64];
    }
}

// ---------------------------------------------------------------------------
// Attention: one block per (b, kvh, 32-query chunk). Online softmax over
// T = 2112 in 64-key tiles; K/V read from the `present` output region.
// 256 threads. Dynamic smem (padded tiles).
// ---------------------------------------------------------------------------
#define QS_STRIDE 132
#define SC_STRIDE 65
#define ATTN_SMEM ((32 * QS_STRIDE + 64 * QS_STRIDE + 64 * QS_STRIDE + 32 * SC_STRIDE + 64) * 4)

__global__ void __launch_bounds__(256) attn_kernel(
    const float* __restrict__ qbuf, const float* __restrict__ kv,
    const int* __restrict__ ctx_len, float* __restrict__ out)
{
    extern __shared__ float sm[];
    float* qs = sm;                        // 32 x 132
    float* ks = qs + 32 * QS_STRIDE;       // 64 x 132
    float* vs = ks + 64 * QS_STRIDE;       // 64 x 132
    float* sc = vs + 64 * QS_STRIDE;       // 32 x 65
    float* corr = sc + 32 * SC_STRIDE;     // 32
    float* lsm = corr + 32;                // 32

    const int tid = threadIdx.x;
    const int blk = blockIdx.x;
    const int qb = blk & 7;
    const int kvh = (blk >> 3) & 3;
    const int b = blk >> 5;

    // load Q tile (32 queries x 128)
    for (int i = tid; i < 32 * 128; i += 256) {
        int ql = i >> 7, d = i & 127;
        int qid = qb * 32 + ql;
        int gi = qid >> 6, s = qid & 63;
        qs[ql * QS_STRIDE + d] =
            qbuf[(((size_t)(b * SEQ + s)) * NQ + (kvh * 4 + gi)) * HDIM + d];
    }

    float acc[16];
#pragma unroll
    for (int i = 0; i < 16; i++) acc[i] = 0.f;
    float m = -INFINITY, l = 0.f;

    const float* Kb = kv + (((size_t)(b * 2 + 0)) * NKV + kvh) * TTOT * HDIM;
    const float* Vb = kv + (((size_t)(b * 2 + 1)) * NKV + kvh) * TTOT * HDIM;
    const int ctx = ctx_len[b];

    const int ql_s = tid >> 3;            // 0..31  (query for scores & AV)
    const int ktg = tid & 7;              // key group
    const int qid_s = qb * 32 + ql_s;
    const int s_q = qid_s & 63;
    const int dg = (tid & 7) * 16;        // dim group for AV

    for (int t0 = 0; t0 < TTOT; t0 += 64) {
        __syncthreads();
        // load K/V tiles
        for (int i = tid * 4; i < 64 * 128; i += 1024) {
            int r = i >> 7, d = i & 127;
            *reinterpret_cast<float4*>(&ks[r * QS_STRIDE + d]) =
                *reinterpret_cast<const float4*>(&Kb[(size_t)(t0 + r) * HDIM + d]);
            *reinterpret_cast<float4*>(&vs[r * QS_STRIDE + d]) =
                *reinterpret_cast<const float4*>(&Vb[(size_t)(t0 + r) * HDIM + d]);
        }
        __syncthreads();
        // scores: each thread: 1 query x 8 keys
        {
            const float* qrow = &qs[ql_s * QS_STRIDE];
#pragma unroll
            for (int j = 0; j < 8; j++) {
                int kt = ktg + 8 * j;
                const float* krow = &ks[kt * QS_STRIDE];
                float dot = 0.f;
#pragma unroll
                for (int d = 0; d < 128; d += 4) {
                    float4 qv = *reinterpret_cast<const float4*>(&qrow[d]);
                    float4 kk = *reinterpret_cast<const float4*>(&krow[d]);
                    dot = fmaf(qv.x, kk.x, dot);
                    dot = fmaf(qv.y, kk.y, dot);
                    dot = fmaf(qv.z, kk.z, dot);
                    dot = fmaf(qv.w, kk.w, dot);
                }
                int t = t0 + kt;
                bool valid = (t < PAST) ? (t < ctx) : ((t - PAST) <= s_q);
                sc[ql_s * SC_STRIDE + kt] =
                    valid ? dot * 0.08838834764831845f : -INFINITY;
            }
        }
        __syncthreads();
        // online softmax (one thread per query)
        if (tid < 32) {
            float mt = -INFINITY;
#pragma unroll 8
            for (int j = 0; j < 64; j++) mt = fmaxf(mt, sc[tid * SC_STRIDE + j]);
            float mnew = fmaxf(m, mt);
            float c, sum = 0.f;
            if (mnew == -INFINITY) {
                c = 1.f;
                for (int j = 0; j < 64; j++) sc[tid * SC_STRIDE + j] = 0.f;
            } else {
                c = __expf(m - mnew);
#pragma unroll 8
                for (int j = 0; j < 64; j++) {
                    float p = __expf(sc[tid * SC_STRIDE + j] - mnew);
                    sc[tid * SC_STRIDE + j] = p;
                    sum += p;
                }
            }
            l = l * c + sum;
            m = mnew;
            corr[tid] = c;
        }
        __syncthreads();
        // accumulate P @ V : each thread: 1 query x 16 dims
        {
            float c = corr[ql_s];
#pragma unroll
            for (int i = 0; i < 16; i++) acc[i] *= c;
            for (int kt = 0; kt < 64; kt++) {
                float p = sc[ql_s * SC_STRIDE + kt];
                const float* vrow = &vs[kt * QS_STRIDE + dg];
#pragma unroll
                for (int i = 0; i < 16; i += 4) {
                    float4 vv = *reinterpret_cast<const float4*>(&vrow[i]);
                    acc[i + 0] = fmaf(p, vv.x, acc[i + 0]);
                    acc[i + 1] = fmaf(p, vv.y, acc[i + 1]);
                    acc[i + 2] = fmaf(p, vv.z, acc[i + 2]);
                    acc[i + 3] = fmaf(p, vv.w, acc[i + 3]);
                }
            }
        }
    }
    if (tid < 32) lsm[tid] = l;
    __syncthreads();
    {
        float linv = 1.f / lsm[ql_s];
        int gi = qid_s >> 6, s = qid_s & 63;
        float* orow = out + (((size_t)(b * SEQ + s)) * NQ + (kvh * 4 + gi)) * HDIM + dg;
#pragma unroll
        for (int i = 0; i < 16; i++) orow[i] = acc[i] * linv;
    }
}

// ---------------------------------------------------------------------------
// In-place log_softmax over VOCAB per row
// ---------------------------------------------------------------------------
__global__ void __launch_bounds__(256) logsoftmax_kernel(float* __restrict__ x)
{
    const int row = blockIdx.x;
    const int tid = threadIdx.x;
    float* xr = x + (size_t)row * VOCAB;
    float mv = -INFINITY;
    for (int i = tid; i < VOCAB; i += 256) mv = fmaxf(mv, xr[i]);
    float M = block_max(mv);
    float s = 0.f;
    for (int i = tid; i < VOCAB; i += 256) s += __expf(xr[i] - M);
    float S = block_sum(s);
    float lse = M + logf(S);
    for (int i = tid; i < VOCAB; i += 256) xr[i] = xr[i] - lse;
}

// ---------------------------------------------------------------------------
// Launch
// ---------------------------------------------------------------------------
extern "C" void kernel_launch(void* const* d_in, const int* in_sizes, int n_in,
                              void* d_out, int out_size)
{
    const float* inputs_embeds = (const float*)d_in[0];
    const float* past_kv       = (const float*)d_in[1];
    const float* rope          = (const float*)d_in[2];
    const int*   ctx_len       = (const int*)d_in[3];
    // d_in[4] kvcache_start_index unused by reference
    const int*   last_ids      = (const int*)d_in[5];
    const float* hsi           = (const float*)d_in[6];
    const float* hsd           = (const float*)d_in[7];
    const int*   pos_id        = (const int*)d_in[8];
    // d_in[9] attention_mask: tril causal — computed arithmetically
    const float* W_fc   = (const float*)d_in[10];
    const float* W_q    = (const float*)d_in[11];
    const float* W_k    = (const float*)d_in[12];
    const float* W_v    = (const float*)d_in[13];
    const float* W_o    = (const float*)d_in[14];
    const float* W_gate = (const float*)d_in[15];
    const float* W_up   = (const float*)d_in[16];
    const float* W_down = (const float*)d_in[17];
    const float* W_lm   = (const float*)d_in[18];
    const float* w_hidden = (const float*)d_in[19];
    const float* w_input  = (const float*)d_in[20];
    const float* w_post   = (const float*)d_in[21];
    const float* w_final  = (const float*)d_in[22];

    float* out = (float*)d_out;
    float* out_logits   = out;
    float* out_gathered = out + LOGITS_ELEMS;
    float* out_present  = out + PRESENT_OFF;

    void* p;
    cudaGetSymbolAddress(&p, g_hs);     float* hs    = (float*)p;
    cudaGetSymbolAddress(&p, g_normed); float* nrm   = (float*)p;
    cudaGetSymbolAddress(&p, g_q);      float* qb    = (float*)p;
    cudaGetSymbolAddress(&p, g_k);      float* kb    = (float*)p;
    cudaGetSymbolAddress(&p, g_v);      float* vb    = (float*)p;
    cudaGetSymbolAddress(&p, g_attn);   float* attnb = (float*)p;
    cudaGetSymbolAddress(&p, g_hn);     float* hn    = (float*)p;
    cudaGetSymbolAddress(&p, g_gate);   float* gateb = (float*)p;
    cudaGetSymbolAddress(&p, g_act);    float* actb  = (float*)p;
    cudaGetSymbolAddress(&p, g_fn);     float* fnb   = (float*)p;

    cudaFuncSetAttribute(attn_kernel, cudaFuncAttributeMaxDynamicSharedMemorySize,
                         ATTN_SMEM);

    // 1. hs = draft + hsi @ W_fc        (256 x 2048 x 6144)
    sgemm128<1><<<dim3(16, 2), 256>>>(hsi, W_fc, hs, hsd, ROWS, HIDDEN, 6144);
    // 2. normed = [rms(emb), rms(hs)]
    rms_concat_kernel<<<ROWS, 256>>>(inputs_embeds, hs, w_input, w_hidden, nrm);
    // 3. q/k/v GEMMs (K = 4096)
    sgemm128<0><<<dim3(16, 2), 256>>>(nrm, W_q, qb, nullptr, ROWS, NQ * HDIM, 4096);
    sgemm128<0><<<dim3(4, 2), 256>>>(nrm, W_k, kb, nullptr, ROWS, NKV * HDIM, 4096);
    sgemm128<0><<<dim3(4, 2), 256>>>(nrm, W_v, vb, nullptr, ROWS, NKV * HDIM, 4096);
    // 4. present: copy past, then roped k / v appended
    copy_past_kernel<<<8192, 256>>>(past_kv, out_present);
    rope_store_kernel<<<dim3(256, 24), 64>>>(qb, kb, vb, rope, pos_id, out_present);
    // 5. attention
    attn_kernel<<<128, 256, ATTN_SMEM>>>(qb, out_present, ctx_len, attnb);
    // 6. hs += attn @ W_o
    sgemm128<1><<<dim3(16, 2), 256>>>(attnb, W_o, hs, hs, ROWS, HIDDEN, 2048);
    // 7. MLP
    rms_kernel<<<ROWS, 256>>>(hs, w_post, hn);
    sgemm128<0><<<dim3(64, 2), 256>>>(hn, W_gate, gateb, nullptr, ROWS, INTER, 2048);
    sgemm128<2><<<dim3(64, 2), 256>>>(hn, W_up, actb, gateb, ROWS, INTER, 2048);
    sgemm128<1><<<dim3(16, 2), 256>>>(actb, W_down, hs, hs, ROWS, HIDDEN, 8192);
    // 8. gather + final norm
    gather_rms_kernel<<<ROWS, 256>>>(hs, last_ids, w_final, out_gathered, fnb);
    // 9. LM head + log_softmax (in place in output)
    sgemm128<0><<<dim3(250, 2), 256>>>(fnb, W_lm, out_logits, nullptr, ROWS, VOCAB, 2048);
    logsoftmax_kernel<<<ROWS, 256>>>(out_logits);
}